// round 1
// baseline (speedup 1.0000x reference)
#include <cuda_runtime.h>
#include <math.h>

// ---------------------------------------------------------------------------
// PartitionedTransformerEncoderLayer  (B=4, S=1024, D_MODEL=1024, H=8,
// D_QKV=128, D_FF=4096, fp32, eval mode)
//
// Pipeline:
//   1. QKV GEMM (both halves, all heads)         -> g_q, g_k, g_v
//   2. dots = Q K^T (batched per (b,h))          -> g_s
//   3. masked softmax over rows of g_s
//   4. O = P V (batched)                         -> g_o  [B,T,H*128]
//   5. O-projection (both halves)                -> g_t1 (attn out)
//   6. LN1(x + attn)                             -> g_x1
//   7. FFN1 (relu, both halves)                  -> g_h
//   8. FFN2 (both halves)                        -> g_t1 (ff out)
//   9. LN2(x1 + ff)                              -> d_out
// ---------------------------------------------------------------------------

#define HH   8
#define TT   1024
#define BB   4
#define DMOD 1024
#define DM2  512
#define DQ   128
#define DQ2  64
#define DF2  2048
#define BT   4096   // B*T

// scratch (device globals are the sanctioned scratch mechanism)
__device__ float g_q[BB*HH*TT*DQ];            // 16 MB
__device__ float g_k[BB*HH*TT*DQ];            // 16 MB
__device__ float g_v[BB*HH*TT*DQ];            // 16 MB
__device__ float g_s[(size_t)BB*HH*TT*TT];    // 128 MB scores
__device__ float g_o[(size_t)BT*DMOD];        // 16 MB  [B,T,H*DQ]
__device__ float g_t1[(size_t)BT*DMOD];       // 16 MB  attn / ff buffer
__device__ float g_x1[(size_t)BT*DMOD];       // 16 MB  post-LN1
__device__ float g_h[(size_t)BT*2*DF2];       // 64 MB  FFN hidden
__device__ float g_maskf[BB*TT];              // canonical mask (1=keep)

// ---------------------------------------------------------------------------
// Mask dtype probe: the reference mask is jnp.bool_; the harness may deliver
// it as int32, float32, or uint8. Classify from the first 4096 bytes (safe
// in-bounds for every interpretation) and canonicalize to float 0/1.
// Order matters: int32 ones (bytes 01 00 00 00) would also pass a byte test,
// so test the word interpretations first. uint8 ones (0x01010101) fail both
// word tests and fall through to the byte path.
// ---------------------------------------------------------------------------
__global__ void mask_probe_k(const void* __restrict__ maskraw) {
    const unsigned int* w = (const unsigned int*)maskraw;
    int tid = threadIdx.x;              // 1024 threads
    unsigned int v = w[tid];            // first 4096 bytes only
    int oki = (v == 0u || v == 1u);
    int okf = (v == 0u || v == 0x3F800000u);
    int all_i = __syncthreads_and(oki);
    int all_f = __syncthreads_and(okf);
    if (all_i) {
        const int* wi = (const int*)maskraw;
        for (int i = tid; i < BB*TT; i += 1024) g_maskf[i] = wi[i] ? 1.f : 0.f;
    } else if (all_f) {
        const float* wf = (const float*)maskraw;
        for (int i = tid; i < BB*TT; i += 1024) g_maskf[i] = (wf[i] != 0.f) ? 1.f : 0.f;
    } else {
        const unsigned char* wb = (const unsigned char*)maskraw;
        for (int i = tid; i < BB*TT; i += 1024) g_maskf[i] = wb[i] ? 1.f : 0.f;
    }
}

// ---------------------------------------------------------------------------
// Generic 64x64x16 fp32 tiled GEMM, 256 threads, 4x4 microtile per thread.
// MODE selects operand addressing + epilogue:
//  0 QKV    : A=x (half sel), B=w_qkv_{c,p} per head, scatter to g_q/g_k/g_v
//  1 DOTS   : A=g_q, B=g_k (K^T), out g_s                (z = b*8+h)
//  2 PV     : A=g_s, B=g_v, out g_o [B,T,H*128]          (z = b*8+h)
//  3 OPROJ  : A=g_o (gather half), B=w_o_{c,p}, out g_t1 (z = half)
//  4 FFN1   : A=g_x1 (half), B=w1^T, +bias, relu -> g_h  (z = half)
//  5 FFN2   : A=g_h (half),  B=w2^T, +bias -> g_t1       (z = half)
// ---------------------------------------------------------------------------
template<int MODE>
__global__ void __launch_bounds__(256)
gemm_k(const float* __restrict__ Aex,
       const float* __restrict__ W0,
       const float* __restrict__ W1,
       const float* __restrict__ bias0,
       const float* __restrict__ bias1,
       float* __restrict__ outex)
{
    constexpr int K = (MODE == 0) ? 512 :
                      (MODE == 1) ? 128 :
                      (MODE == 2) ? 1024 :
                      (MODE == 3) ? 512 :
                      (MODE == 4) ? 512 : 2048;

    __shared__ float As[64][17];   // [m][k], padded vs bank conflicts
    __shared__ float Bs[16][68];   // [k][n], padded

    const int tid = threadIdx.x;
    const int tx = tid & 15, ty = tid >> 4;
    const int m0 = blockIdx.y * 64;
    const int n0 = blockIdx.x * 64;
    const int z  = blockIdx.z;

    const float* Abase;
    if constexpr (MODE == 0)      Abase = Aex;
    else if constexpr (MODE == 1) Abase = g_q;
    else if constexpr (MODE == 2) Abase = g_s;
    else if constexpr (MODE == 3) Abase = g_o;
    else if constexpr (MODE == 4) Abase = g_x1;
    else                          Abase = g_h;

    float acc[4][4];
#pragma unroll
    for (int i = 0; i < 4; i++)
#pragma unroll
        for (int j = 0; j < 4; j++) acc[i][j] = 0.f;

    for (int k0 = 0; k0 < K; k0 += 16) {
        // ---- load A tile (64 x 16) ----
        {
            int ml = tid >> 2;
            int kq = (tid & 3) << 2;
            int m = m0 + ml, k = k0 + kq;
            size_t ai;
            if constexpr (MODE == 0)
                ai = (size_t)m * DMOD + (size_t)(z >> 3) * DM2 + k;
            else if constexpr (MODE == 1)
                ai = (size_t)z * (TT*DQ) + (size_t)m * DQ + k;
            else if constexpr (MODE == 2)
                ai = (size_t)z * ((size_t)TT*TT) + (size_t)m * TT + k;
            else if constexpr (MODE == 3)
                ai = (size_t)m * DMOD + (size_t)((k >> 6) << 7) + (size_t)z * DQ2 + (k & 63);
            else if constexpr (MODE == 4)
                ai = (size_t)m * DMOD + (size_t)z * DM2 + k;
            else
                ai = (size_t)m * (2*DF2) + (size_t)z * DF2 + k;
            float4 av = *(const float4*)(Abase + ai);
            As[ml][kq + 0] = av.x; As[ml][kq + 1] = av.y;
            As[ml][kq + 2] = av.z; As[ml][kq + 3] = av.w;
        }
        // ---- load B tile (16 x 64) ----
        if constexpr (MODE == 0 || MODE == 2 || MODE == 3) {
            // B is k-row-major contiguous in n
            int kk = tid >> 4;
            int nq = (tid & 15) << 2;
            int k = k0 + kk, n = n0 + nq;
            const float* Wb; size_t bi;
            if constexpr (MODE == 0) {
                Wb = ((z >> 3) ? W1 : W0) + (size_t)(z & 7) * (DM2 * 192);
                bi = (size_t)k * 192 + n;
            } else if constexpr (MODE == 2) {
                Wb = g_v + (size_t)z * (TT*DQ);
                bi = (size_t)k * DQ + n;
            } else {
                Wb = z ? W1 : W0;
                bi = (size_t)k * DM2 + n;
            }
            float4 bv = *(const float4*)(Wb + bi);
            *(float4*)&Bs[kk][nq] = bv;
        } else {
            // B is n-major (contiguous in k): transpose while loading
            int nl = tid >> 2;
            int kq = (tid & 3) << 2;
            int n = n0 + nl, k = k0 + kq;
            const float* Wb; size_t bi;
            if constexpr (MODE == 1) {
                Wb = g_k + (size_t)z * (TT*DQ);
                bi = (size_t)n * DQ + k;
            } else if constexpr (MODE == 4) {
                Wb = z ? W1 : W0;
                bi = (size_t)n * DM2 + k;
            } else {
                Wb = z ? W1 : W0;
                bi = (size_t)n * DF2 + k;
            }
            float4 bv = *(const float4*)(Wb + bi);
            Bs[kq + 0][nl] = bv.x; Bs[kq + 1][nl] = bv.y;
            Bs[kq + 2][nl] = bv.z; Bs[kq + 3][nl] = bv.w;
        }
        __syncthreads();

        // ---- compute ----
#pragma unroll
        for (int kk = 0; kk < 16; kk++) {
            float a0 = As[ty*4 + 0][kk];
            float a1 = As[ty*4 + 1][kk];
            float a2 = As[ty*4 + 2][kk];
            float a3 = As[ty*4 + 3][kk];
            float4 bv = *(const float4*)&Bs[kk][tx*4];
            acc[0][0] += a0*bv.x; acc[0][1] += a0*bv.y; acc[0][2] += a0*bv.z; acc[0][3] += a0*bv.w;
            acc[1][0] += a1*bv.x; acc[1][1] += a1*bv.y; acc[1][2] += a1*bv.z; acc[1][3] += a1*bv.w;
            acc[2][0] += a2*bv.x; acc[2][1] += a2*bv.y; acc[2][2] += a2*bv.z; acc[2][3] += a2*bv.w;
            acc[3][0] += a3*bv.x; acc[3][1] += a3*bv.y; acc[3][2] += a3*bv.z; acc[3][3] += a3*bv.w;
        }
        __syncthreads();
    }

    // ---- epilogue ----
    if constexpr (MODE == 0) {
        const int cc  = blockIdx.x;          // 0=q 1=k 2=v (BN=64 aligns with cc blocks)
        const int h   = z & 7, sel = z >> 3;
        const float scale = (cc == 0) ? 0.08838834764831845f : 1.0f;
        float* dst = (cc == 0) ? g_q : ((cc == 1) ? g_k : g_v);
#pragma unroll
        for (int i = 0; i < 4; i++) {
            int m = m0 + ty*4 + i;
            int b = m >> 10, t = m & 1023;
            size_t base = ((((size_t)b*HH + h)*TT + t) << 7) + ((size_t)sel << 6);
#pragma unroll
            for (int j = 0; j < 4; j++) {
                int a = tx*4 + j;            // n0 = cc*64, local col == a
                dst[base + a] = acc[i][j] * scale;
            }
        }
    } else if constexpr (MODE == 1) {
#pragma unroll
        for (int i = 0; i < 4; i++) {
            int m = m0 + ty*4 + i;
            size_t base = (size_t)z * ((size_t)TT*TT) + (size_t)m * TT + n0;
#pragma unroll
            for (int j = 0; j < 4; j++)
                g_s[base + tx*4 + j] = acc[i][j];
        }
    } else if constexpr (MODE == 2) {
        const int b = z >> 3, h = z & 7;
#pragma unroll
        for (int i = 0; i < 4; i++) {
            int m = m0 + ty*4 + i;   // = t
            size_t base = ((size_t)(b*TT + m)) * DMOD + h*DQ + n0;
#pragma unroll
            for (int j = 0; j < 4; j++)
                g_o[base + tx*4 + j] = acc[i][j];
        }
    } else if constexpr (MODE == 3) {
#pragma unroll
        for (int i = 0; i < 4; i++) {
            int m = m0 + ty*4 + i;
            size_t base = (size_t)m * DMOD + (size_t)z * DM2 + n0;
#pragma unroll
            for (int j = 0; j < 4; j++)
                g_t1[base + tx*4 + j] = acc[i][j];
        }
    } else if constexpr (MODE == 4) {
        const float* bs = z ? bias1 : bias0;
#pragma unroll
        for (int i = 0; i < 4; i++) {
            int m = m0 + ty*4 + i;
            size_t base = (size_t)m * (2*DF2) + (size_t)z * DF2 + n0;
#pragma unroll
            for (int j = 0; j < 4; j++) {
                int n = n0 + tx*4 + j;
                g_h[base + tx*4 + j] = fmaxf(acc[i][j] + bs[n], 0.f);
            }
        }
    } else { // MODE == 5
        const float* bs = z ? bias1 : bias0;
#pragma unroll
        for (int i = 0; i < 4; i++) {
            int m = m0 + ty*4 + i;
            size_t base = (size_t)m * DMOD + (size_t)z * DM2 + n0;
#pragma unroll
            for (int j = 0; j < 4; j++) {
                int n = n0 + tx*4 + j;
                g_t1[base + tx*4 + j] = acc[i][j] + bs[n];
            }
        }
    }
    (void)outex;
}

// ---------------------------------------------------------------------------
// Row softmax over g_s with mask (one block per row of 1024)
// ---------------------------------------------------------------------------
__global__ void __launch_bounds__(256) softmax_k()
{
    const int row = blockIdx.x;              // z*1024 + t
    const int zz = row >> 10;
    const int b = zz >> 3;
    float* S = g_s + (size_t)row * TT;
    const float* mrow = g_maskf + b * TT;
    const int tid = threadIdx.x;

    __shared__ float red[256];

    float vals[4];
    float mx = -INFINITY;
#pragma unroll
    for (int i = 0; i < 4; i++) {
        int c = tid + i * 256;
        float v = (mrow[c] != 0.f) ? S[c] : -INFINITY;
        vals[i] = v;
        mx = fmaxf(mx, v);
    }
    red[tid] = mx; __syncthreads();
    for (int s = 128; s > 0; s >>= 1) {
        if (tid < s) red[tid] = fmaxf(red[tid], red[tid + s]);
        __syncthreads();
    }
    mx = red[0]; __syncthreads();

    float sum = 0.f;
#pragma unroll
    for (int i = 0; i < 4; i++) {
        float e = (vals[i] == -INFINITY) ? 0.f : expf(vals[i] - mx);
        vals[i] = e;
        sum += e;
    }
    red[tid] = sum; __syncthreads();
    for (int s = 128; s > 0; s >>= 1) {
        if (tid < s) red[tid] += red[tid + s];
        __syncthreads();
    }
    float inv = 1.0f / red[0];
#pragma unroll
    for (int i = 0; i < 4; i++)
        S[tid + i * 256] = vals[i] * inv;
}

// ---------------------------------------------------------------------------
// Fused residual + LayerNorm. PHASE 0: g_x1 = LN(x + g_t1)
//                             PHASE 1: out  = LN(g_x1 + g_t1)
// ---------------------------------------------------------------------------
template<int PHASE>
__global__ void __launch_bounds__(256)
ln_k(const float* __restrict__ a,
     const float* __restrict__ gamma,
     const float* __restrict__ beta,
     float* __restrict__ outp)
{
    const int row = blockIdx.x;
    const int tid = threadIdx.x;
    const float* r1 = (PHASE == 0) ? a : g_x1;

    __shared__ float red[256];

    float v[4];
    float s = 0.f;
#pragma unroll
    for (int i = 0; i < 4; i++) {
        int c = tid + i * 256;
        float t = r1[(size_t)row * DMOD + c] + g_t1[(size_t)row * DMOD + c];
        v[i] = t;
        s += t;
    }
    red[tid] = s; __syncthreads();
    for (int st = 128; st > 0; st >>= 1) {
        if (tid < st) red[tid] += red[tid + st];
        __syncthreads();
    }
    const float mu = red[0] * (1.0f / DMOD);
    __syncthreads();

    float vs = 0.f;
#pragma unroll
    for (int i = 0; i < 4; i++) {
        float d = v[i] - mu;
        vs += d * d;
    }
    red[tid] = vs; __syncthreads();
    for (int st = 128; st > 0; st >>= 1) {
        if (tid < st) red[tid] += red[tid + st];
        __syncthreads();
    }
    const float var = red[0] * (1.0f / DMOD);
    const float rs = rsqrtf(var + 1e-5f);

    float* o = (PHASE == 0) ? g_x1 : outp;
#pragma unroll
    for (int i = 0; i < 4; i++) {
        int c = tid + i * 256;
        o[(size_t)row * DMOD + c] = (v[i] - mu) * rs * gamma[c] + beta[c];
    }
}

// ---------------------------------------------------------------------------
extern "C" void kernel_launch(void* const* d_in, const int* in_sizes, int n_in,
                              void* d_out, int out_size)
{
    (void)in_sizes; (void)n_in; (void)out_size;
    const float* x      = (const float*)d_in[0];
    const void*  mask   = d_in[1];
    const float* wqkv_c = (const float*)d_in[2];
    const float* wqkv_p = (const float*)d_in[3];
    const float* wo_c   = (const float*)d_in[4];
    const float* wo_p   = (const float*)d_in[5];
    const float* w1_c   = (const float*)d_in[6];
    const float* b1_c   = (const float*)d_in[7];
    const float* w1_p   = (const float*)d_in[8];
    const float* b1_p   = (const float*)d_in[9];
    const float* w2_c   = (const float*)d_in[10];
    const float* b2_c   = (const float*)d_in[11];
    const float* w2_p   = (const float*)d_in[12];
    const float* b2_p   = (const float*)d_in[13];
    const float* ln1_g  = (const float*)d_in[14];
    const float* ln1_b  = (const float*)d_in[15];
    const float* ln2_g  = (const float*)d_in[16];
    const float* ln2_b  = (const float*)d_in[17];
    float* out = (float*)d_out;

    mask_probe_k<<<1, 1024>>>(mask);

    // 1. QKV: per head N=192 (3 tiles of 64), z = sel*8 + h
    gemm_k<0><<<dim3(3, 64, 16), 256>>>(x, wqkv_c, wqkv_p, nullptr, nullptr, nullptr);
    // 2. dots = Q K^T, batched over z = b*8+h
    gemm_k<1><<<dim3(16, 16, 32), 256>>>(nullptr, nullptr, nullptr, nullptr, nullptr, nullptr);
    // 3. masked softmax
    softmax_k<<<BB*HH*TT, 256>>>();
    // 4. O = P V
    gemm_k<2><<<dim3(2, 16, 32), 256>>>(nullptr, nullptr, nullptr, nullptr, nullptr, nullptr);
    // 5. O projection (z = half)
    gemm_k<3><<<dim3(8, 64, 2), 256>>>(nullptr, wo_c, wo_p, nullptr, nullptr, nullptr);
    // 6. LN1(x + attn) -> g_x1
    ln_k<0><<<BT, 256>>>(x, ln1_g, ln1_b, nullptr);
    // 7. FFN1 (relu)
    gemm_k<4><<<dim3(32, 64, 2), 256>>>(nullptr, w1_c, w1_p, b1_c, b1_p, nullptr);
    // 8. FFN2
    gemm_k<5><<<dim3(8, 64, 2), 256>>>(nullptr, w2_c, w2_p, b2_c, b2_p, nullptr);
    // 9. LN2(x1 + ff) -> out
    ln_k<1><<<BT, 256>>>(nullptr, ln2_g, ln2_b, out);
}

// round 2
// speedup vs baseline: 2.2401x; 2.2401x over previous
#include <cuda_runtime.h>
#include <math.h>
#include <stdint.h>

// ---------------------------------------------------------------------------
// PartitionedTransformerEncoderLayer — Round 2: TF32 tensor-core GEMMs
// (B=4, S=1024, D_MODEL=1024, H=8, D_QKV=128, D_FF=4096, fp32 in/out)
// ---------------------------------------------------------------------------

#define HH   8
#define TT   1024
#define BB   4
#define DMOD 1024
#define DM2  512
#define DQ   128
#define DQ2  64
#define DF2  2048
#define BT   4096   // B*T

// scratch
__device__ float g_q[BB*HH*TT*DQ];
__device__ float g_k[BB*HH*TT*DQ];
__device__ float g_v[BB*HH*TT*DQ];
__device__ float g_s[(size_t)BB*HH*TT*TT];
__device__ float g_o[(size_t)BT*DMOD];
__device__ float g_t1[(size_t)BT*DMOD];
__device__ float g_x1[(size_t)BT*DMOD];
__device__ float g_h[(size_t)BT*2*DF2];
__device__ float g_maskf[BB*TT];

// ---------------------------------------------------------------------------
// Mask canonicalization (bool may arrive as int32 / float32 / uint8)
// ---------------------------------------------------------------------------
__global__ void mask_probe_k(const void* __restrict__ maskraw) {
    const unsigned int* w = (const unsigned int*)maskraw;
    int tid = threadIdx.x;
    unsigned int v = w[tid];
    int oki = (v == 0u || v == 1u);
    int okf = (v == 0u || v == 0x3F800000u);
    int all_i = __syncthreads_and(oki);
    int all_f = __syncthreads_and(okf);
    if (all_i) {
        const int* wi = (const int*)maskraw;
        for (int i = tid; i < BB*TT; i += 1024) g_maskf[i] = wi[i] ? 1.f : 0.f;
    } else if (all_f) {
        const float* wf = (const float*)maskraw;
        for (int i = tid; i < BB*TT; i += 1024) g_maskf[i] = (wf[i] != 0.f) ? 1.f : 0.f;
    } else {
        const unsigned char* wb = (const unsigned char*)maskraw;
        for (int i = tid; i < BB*TT; i += 1024) g_maskf[i] = wb[i] ? 1.f : 0.f;
    }
}

// ---------------------------------------------------------------------------
// tf32 helpers
// ---------------------------------------------------------------------------
__device__ __forceinline__ unsigned f2tf32(float f) {
    unsigned u;
    asm("cvt.rna.tf32.f32 %0, %1;" : "=r"(u) : "f"(f));
    return u;
}

__device__ __forceinline__ void ldm_x4(unsigned &r0, unsigned &r1,
                                       unsigned &r2, unsigned &r3,
                                       const unsigned* p) {
    unsigned addr = (unsigned)__cvta_generic_to_shared(p);
    asm volatile("ldmatrix.sync.aligned.m8n8.x4.shared.b16 {%0,%1,%2,%3}, [%4];"
                 : "=r"(r0), "=r"(r1), "=r"(r2), "=r"(r3) : "r"(addr));
}

__device__ __forceinline__ void mma_tf32(float* c, const unsigned* a, const unsigned* b) {
    asm volatile("mma.sync.aligned.m16n8k8.row.col.f32.tf32.tf32.f32 "
                 "{%0,%1,%2,%3}, {%4,%5,%6,%7}, {%8,%9}, {%0,%1,%2,%3};"
                 : "+f"(c[0]), "+f"(c[1]), "+f"(c[2]), "+f"(c[3])
                 : "r"(a[0]), "r"(a[1]), "r"(a[2]), "r"(a[3]),
                   "r"(b[0]), "r"(b[1]));
}

// ---------------------------------------------------------------------------
// TF32 GEMM: block tile 128(M) x 64(N) x 32(K), 256 threads = 8 warps (4Mx2N),
// warp tile 32x32 -> 2 m16 x 4 n8 mma tiles. ldmatrix for A and B fragments.
// MODE operand map (same as round 1):
//  0 QKV  : A=x (half via z>>3), B=w_qkv per head (n-contig), -> g_q/g_k/g_v
//  1 DOTS : A=g_q, B=g_k (k-contig), -> g_s                  (z = b*8+h)
//  2 PV   : A=g_s, B=g_v (n-contig), -> g_o [B,T,H*128]      (z = b*8+h)
//  3 OPROJ: A=g_o gather, B=w_o (n-contig), -> g_t1          (z = half)
//  4 FFN1 : A=g_x1, B=w1 (k-contig), +bias relu -> g_h       (z = half)
//  5 FFN2 : A=g_h,  B=w2 (k-contig), +bias -> g_t1           (z = half)
// ---------------------------------------------------------------------------
template<int MODE>
__global__ void __launch_bounds__(256)
gemm_tc(const float* __restrict__ Aex,
        const float* __restrict__ W0,
        const float* __restrict__ W1,
        const float* __restrict__ bias0,
        const float* __restrict__ bias1)
{
    constexpr int K = (MODE == 0) ? 512 :
                      (MODE == 1) ? 128 :
                      (MODE == 2) ? 1024 :
                      (MODE == 3) ? 512 :
                      (MODE == 4) ? 512 : 2048;
    constexpr bool B_KCONTIG = (MODE == 1 || MODE == 4 || MODE == 5);

    __shared__ unsigned As[128][36];   // [m][k] words, stride 36 -> ldmatrix conflict-free
    __shared__ unsigned Bs[64][36];    // [n][k]

    const int tid  = threadIdx.x;
    const int lane = tid & 31;
    const int warp = tid >> 5;
    const int wm = (warp & 3) * 32;
    const int wn = (warp >> 2) * 32;
    const int m0 = blockIdx.y * 128;
    const int n0 = blockIdx.x * 64;
    const int z  = blockIdx.z;

    const float* Abase;
    if constexpr (MODE == 0)      Abase = Aex;
    else if constexpr (MODE == 1) Abase = g_q;
    else if constexpr (MODE == 2) Abase = g_s;
    else if constexpr (MODE == 3) Abase = g_o;
    else if constexpr (MODE == 4) Abase = g_x1;
    else                          Abase = g_h;

    // B base pointer + row stride
    const float* Wb;
    int bstride;
    if constexpr (MODE == 0) { Wb = ((z >> 3) ? W1 : W0) + (size_t)(z & 7) * (DM2 * 192); bstride = 192; }
    else if constexpr (MODE == 1) { Wb = g_k + (size_t)z * (TT*DQ); bstride = DQ;  }
    else if constexpr (MODE == 2) { Wb = g_v + (size_t)z * (TT*DQ); bstride = DQ;  }
    else if constexpr (MODE == 3) { Wb = z ? W1 : W0;               bstride = DM2; }
    else if constexpr (MODE == 4) { Wb = z ? W1 : W0;               bstride = DM2; }
    else                          { Wb = z ? W1 : W0;               bstride = DF2; }

    float c[2][4][4];
#pragma unroll
    for (int mt = 0; mt < 2; mt++)
#pragma unroll
        for (int nt = 0; nt < 4; nt++)
#pragma unroll
            for (int r = 0; r < 4; r++) c[mt][nt][r] = 0.f;

    // A loader indices: 4 rows of 32 per iter
    const int a_ml = tid >> 3;          // 0..31
    const int a_kq = (tid & 7) << 2;    // 0,4,..,28
    // B loaders
    const int bk_nl = tid >> 3;         // k-contig path: n row 0..31
    const int bk_kq = (tid & 7) << 2;
    const int bt_kl = tid >> 4;         // transpose path: k row 0..15
    const int bt_nq = (tid & 15) << 2;

    for (int k0 = 0; k0 < K; k0 += 32) {
        // ---- A tile 128x32 ----
#pragma unroll
        for (int it = 0; it < 4; it++) {
            int m = m0 + a_ml + it * 32;
            int k = k0 + a_kq;
            size_t ai;
            if constexpr (MODE == 0)
                ai = (size_t)m * DMOD + (size_t)(z >> 3) * DM2 + k;
            else if constexpr (MODE == 1)
                ai = (size_t)z * (TT*DQ) + (size_t)m * DQ + k;
            else if constexpr (MODE == 2)
                ai = (size_t)z * ((size_t)TT*TT) + (size_t)m * TT + k;
            else if constexpr (MODE == 3)
                ai = (size_t)m * DMOD + (size_t)((k >> 6) << 7) + (size_t)z * DQ2 + (k & 63);
            else if constexpr (MODE == 4)
                ai = (size_t)m * DMOD + (size_t)z * DM2 + k;
            else
                ai = (size_t)m * (2*DF2) + (size_t)z * DF2 + k;
            float4 av = *(const float4*)(Abase + ai);
            uint4 tv;
            tv.x = f2tf32(av.x); tv.y = f2tf32(av.y);
            tv.z = f2tf32(av.z); tv.w = f2tf32(av.w);
            *(uint4*)&As[a_ml + it * 32][a_kq] = tv;
        }
        // ---- B tile 64n x 32k ----
        if constexpr (B_KCONTIG) {
#pragma unroll
            for (int it = 0; it < 2; it++) {
                int n = n0 + bk_nl + it * 32;
                int k = k0 + bk_kq;
                float4 bv = *(const float4*)(Wb + (size_t)n * bstride + k);
                uint4 tv;
                tv.x = f2tf32(bv.x); tv.y = f2tf32(bv.y);
                tv.z = f2tf32(bv.z); tv.w = f2tf32(bv.w);
                *(uint4*)&Bs[bk_nl + it * 32][bk_kq] = tv;
            }
        } else {
#pragma unroll
            for (int it = 0; it < 2; it++) {
                int k = k0 + bt_kl + it * 16;
                int n = n0 + bt_nq;
                float4 bv = *(const float4*)(Wb + (size_t)k * bstride + n);
                Bs[bt_nq + 0][bt_kl + it * 16] = f2tf32(bv.x);
                Bs[bt_nq + 1][bt_kl + it * 16] = f2tf32(bv.y);
                Bs[bt_nq + 2][bt_kl + it * 16] = f2tf32(bv.z);
                Bs[bt_nq + 3][bt_kl + it * 16] = f2tf32(bv.w);
            }
        }
        __syncthreads();

        // ---- compute: 4 k8 steps ----
        const int grp = lane >> 3;       // ldmatrix sub-matrix selector
        const int rr  = lane & 7;
#pragma unroll
        for (int ks = 0; ks < 4; ks++) {
            const int kw = ks * 8;
            unsigned a[2][4];
#pragma unroll
            for (int mt = 0; mt < 2; mt++) {
                const unsigned* p = &As[wm + mt*16 + (grp & 1)*8 + rr][kw + (grp >> 1)*4];
                ldm_x4(a[mt][0], a[mt][1], a[mt][2], a[mt][3], p);
            }
            unsigned b[4][2];
#pragma unroll
            for (int bt = 0; bt < 2; bt++) {
                const unsigned* p = &Bs[wn + bt*16 + (grp >> 1)*8 + rr][kw + (grp & 1)*4];
                unsigned r0, r1, r2, r3;
                ldm_x4(r0, r1, r2, r3, p);
                b[bt*2 + 0][0] = r0; b[bt*2 + 0][1] = r1;
                b[bt*2 + 1][0] = r2; b[bt*2 + 1][1] = r3;
            }
#pragma unroll
            for (int mt = 0; mt < 2; mt++)
#pragma unroll
                for (int nt = 0; nt < 4; nt++)
                    mma_tf32(c[mt][nt], a[mt], b[nt]);
        }
        __syncthreads();
    }

    // ---- epilogue ----
    const int g   = lane >> 2;
    const int tig = lane & 3;

#pragma unroll
    for (int mt = 0; mt < 2; mt++) {
#pragma unroll
        for (int nt = 0; nt < 4; nt++) {
            const int mr = m0 + wm + mt*16 + g;       // row of c0/c1; c2/c3 at +8
            const int nl = wn + nt*8 + 2*tig;         // local col within 64-tile
            float2 lo = make_float2(c[mt][nt][0], c[mt][nt][1]);
            float2 hi = make_float2(c[mt][nt][2], c[mt][nt][3]);

            if constexpr (MODE == 0) {
                const int cc = blockIdx.x;            // 0=q 1=k 2=v
                const int h = z & 7, sel = z >> 3;
                const float scale = (cc == 0) ? 0.08838834764831845f : 1.0f;
                float* dst = (cc == 0) ? g_q : ((cc == 1) ? g_k : g_v);
                lo.x *= scale; lo.y *= scale; hi.x *= scale; hi.y *= scale;
                {
                    int b_ = mr >> 10, t_ = mr & 1023;
                    size_t base = ((((size_t)b_*HH + h)*TT + t_) << 7) + ((size_t)sel << 6);
                    *(float2*)(dst + base + nl) = lo;
                }
                {
                    int m2 = mr + 8;
                    int b_ = m2 >> 10, t_ = m2 & 1023;
                    size_t base = ((((size_t)b_*HH + h)*TT + t_) << 7) + ((size_t)sel << 6);
                    *(float2*)(dst + base + nl) = hi;
                }
            } else if constexpr (MODE == 1) {
                size_t base = (size_t)z * ((size_t)TT*TT);
                *(float2*)(g_s + base + (size_t)mr * TT + n0 + nl) = lo;
                *(float2*)(g_s + base + (size_t)(mr+8) * TT + n0 + nl) = hi;
            } else if constexpr (MODE == 2) {
                const int b_ = z >> 3, h = z & 7;
                size_t r0 = ((size_t)(b_*TT + mr)) * DMOD + h*DQ + n0 + nl;
                size_t r1 = ((size_t)(b_*TT + mr + 8)) * DMOD + h*DQ + n0 + nl;
                *(float2*)(g_o + r0) = lo;
                *(float2*)(g_o + r1) = hi;
            } else if constexpr (MODE == 3) {
                size_t r0 = (size_t)mr * DMOD + (size_t)z * DM2 + n0 + nl;
                *(float2*)(g_t1 + r0) = lo;
                *(float2*)(g_t1 + r0 + 8*DMOD) = hi;
            } else if constexpr (MODE == 4) {
                const float* bs = z ? bias1 : bias0;
                float b0 = bs[n0 + nl], b1 = bs[n0 + nl + 1];
                size_t r0 = (size_t)mr * (2*DF2) + (size_t)z * DF2 + n0 + nl;
                float2 o0 = make_float2(fmaxf(lo.x + b0, 0.f), fmaxf(lo.y + b1, 0.f));
                float2 o1 = make_float2(fmaxf(hi.x + b0, 0.f), fmaxf(hi.y + b1, 0.f));
                *(float2*)(g_h + r0) = o0;
                *(float2*)(g_h + r0 + (size_t)8 * (2*DF2)) = o1;
            } else {
                const float* bs = z ? bias1 : bias0;
                float b0 = bs[n0 + nl], b1 = bs[n0 + nl + 1];
                size_t r0 = (size_t)mr * DMOD + (size_t)z * DM2 + n0 + nl;
                float2 o0 = make_float2(lo.x + b0, lo.y + b1);
                float2 o1 = make_float2(hi.x + b0, hi.y + b1);
                *(float2*)(g_t1 + r0) = o0;
                *(float2*)(g_t1 + r0 + 8*DMOD) = o1;
            }
        }
    }
}

// ---------------------------------------------------------------------------
// Row softmax over g_s with mask (one block per row of 1024)
// ---------------------------------------------------------------------------
__global__ void __launch_bounds__(256) softmax_k()
{
    const int row = blockIdx.x;
    const int zz = row >> 10;
    const int b = zz >> 3;
    float* S = g_s + (size_t)row * TT;
    const float* mrow = g_maskf + b * TT;
    const int tid = threadIdx.x;

    __shared__ float red[256];

    float vals[4];
    float mx = -INFINITY;
#pragma unroll
    for (int i = 0; i < 4; i++) {
        int cidx = tid + i * 256;
        float v = (mrow[cidx] != 0.f) ? S[cidx] : -INFINITY;
        vals[i] = v;
        mx = fmaxf(mx, v);
    }
    red[tid] = mx; __syncthreads();
    for (int s = 128; s > 0; s >>= 1) {
        if (tid < s) red[tid] = fmaxf(red[tid], red[tid + s]);
        __syncthreads();
    }
    mx = red[0]; __syncthreads();

    float sum = 0.f;
#pragma unroll
    for (int i = 0; i < 4; i++) {
        float e = (vals[i] == -INFINITY) ? 0.f : expf(vals[i] - mx);
        vals[i] = e;
        sum += e;
    }
    red[tid] = sum; __syncthreads();
    for (int s = 128; s > 0; s >>= 1) {
        if (tid < s) red[tid] += red[tid + s];
        __syncthreads();
    }
    float inv = 1.0f / red[0];
#pragma unroll
    for (int i = 0; i < 4; i++)
        S[tid + i * 256] = vals[i] * inv;
}

// ---------------------------------------------------------------------------
// Fused residual + LayerNorm
// ---------------------------------------------------------------------------
template<int PHASE>
__global__ void __launch_bounds__(256)
ln_k(const float* __restrict__ a,
     const float* __restrict__ gamma,
     const float* __restrict__ beta,
     float* __restrict__ outp)
{
    const int row = blockIdx.x;
    const int tid = threadIdx.x;
    const float* r1 = (PHASE == 0) ? a : g_x1;

    __shared__ float red[256];

    float v[4];
    float s = 0.f;
#pragma unroll
    for (int i = 0; i < 4; i++) {
        int cidx = tid + i * 256;
        float t = r1[(size_t)row * DMOD + cidx] + g_t1[(size_t)row * DMOD + cidx];
        v[i] = t;
        s += t;
    }
    red[tid] = s; __syncthreads();
    for (int st = 128; st > 0; st >>= 1) {
        if (tid < st) red[tid] += red[tid + st];
        __syncthreads();
    }
    const float mu = red[0] * (1.0f / DMOD);
    __syncthreads();

    float vs = 0.f;
#pragma unroll
    for (int i = 0; i < 4; i++) {
        float d = v[i] - mu;
        vs += d * d;
    }
    red[tid] = vs; __syncthreads();
    for (int st = 128; st > 0; st >>= 1) {
        if (tid < st) red[tid] += red[tid + st];
        __syncthreads();
    }
    const float var = red[0] * (1.0f / DMOD);
    const float rs = rsqrtf(var + 1e-5f);

    float* o = (PHASE == 0) ? g_x1 : outp;
#pragma unroll
    for (int i = 0; i < 4; i++) {
        int cidx = tid + i * 256;
        o[(size_t)row * DMOD + cidx] = (v[i] - mu) * rs * gamma[cidx] + beta[cidx];
    }
}

// ---------------------------------------------------------------------------
extern "C" void kernel_launch(void* const* d_in, const int* in_sizes, int n_in,
                              void* d_out, int out_size)
{
    (void)in_sizes; (void)n_in; (void)out_size;
    const float* x      = (const float*)d_in[0];
    const void*  mask   = d_in[1];
    const float* wqkv_c = (const float*)d_in[2];
    const float* wqkv_p = (const float*)d_in[3];
    const float* wo_c   = (const float*)d_in[4];
    const float* wo_p   = (const float*)d_in[5];
    const float* w1_c   = (const float*)d_in[6];
    const float* b1_c   = (const float*)d_in[7];
    const float* w1_p   = (const float*)d_in[8];
    const float* b1_p   = (const float*)d_in[9];
    const float* w2_c   = (const float*)d_in[10];
    const float* b2_c   = (const float*)d_in[11];
    const float* w2_p   = (const float*)d_in[12];
    const float* b2_p   = (const float*)d_in[13];
    const float* ln1_g  = (const float*)d_in[14];
    const float* ln1_b  = (const float*)d_in[15];
    const float* ln2_g  = (const float*)d_in[16];
    const float* ln2_b  = (const float*)d_in[17];
    float* out = (float*)d_out;

    mask_probe_k<<<1, 1024>>>(mask);

    // 1. QKV (bx=q/k/v, by m-tile, z=sel*8+h)
    gemm_tc<0><<<dim3(3, 32, 16), 256>>>(x, wqkv_c, wqkv_p, nullptr, nullptr);
    // 2. dots = Q K^T
    gemm_tc<1><<<dim3(16, 8, 32), 256>>>(nullptr, nullptr, nullptr, nullptr, nullptr);
    // 3. masked softmax
    softmax_k<<<BB*HH*TT, 256>>>();
    // 4. O = P V
    gemm_tc<2><<<dim3(2, 8, 32), 256>>>(nullptr, nullptr, nullptr, nullptr, nullptr);
    // 5. O projection
    gemm_tc<3><<<dim3(8, 32, 2), 256>>>(nullptr, wo_c, wo_p, nullptr, nullptr);
    // 6. LN1(x + attn) -> g_x1
    ln_k<0><<<BT, 256>>>(x, ln1_g, ln1_b, nullptr);
    // 7. FFN1 (relu)
    gemm_tc<4><<<dim3(32, 32, 2), 256>>>(nullptr, w1_c, w1_p, b1_c, b1_p);
    // 8. FFN2
    gemm_tc<5><<<dim3(8, 32, 2), 256>>>(nullptr, w2_c, w2_p, b2_c, b2_p);
    // 9. LN2(x1 + ff) -> out
    ln_k<1><<<BT, 256>>>(nullptr, ln2_g, ln2_b, out);
}

// round 3
// speedup vs baseline: 3.1023x; 1.3849x over previous
#include <cuda_runtime.h>
#include <math.h>
#include <stdint.h>

// ---------------------------------------------------------------------------
// PartitionedTransformerEncoderLayer — Round 3: tf32 tensor cores +
// cp.async double-buffered GEMM + shuffle softmax/LN
// ---------------------------------------------------------------------------

#define HH   8
#define TT   1024
#define BB   4
#define DMOD 1024
#define DM2  512
#define DQ   128
#define DQ2  64
#define DF2  2048
#define BT   4096

// scratch
__device__ float g_q[BB*HH*TT*DQ];
__device__ float g_k[BB*HH*TT*DQ];
__device__ float g_v[BB*HH*TT*DQ];
__device__ float g_s[(size_t)BB*HH*TT*TT];
__device__ float g_o[(size_t)BT*DMOD];
__device__ float g_t1[(size_t)BT*DMOD];
__device__ float g_x1[(size_t)BT*DMOD];   // fp32 (residual)
__device__ float g_x1r[(size_t)BT*DMOD];  // tf32-rounded (FFN1 operand)
__device__ float g_h[(size_t)BT*2*DF2];
__device__ float g_maskf[BB*TT];
// tf32-rounded copies of external operands
__device__ float g_xr[(size_t)BT*DMOD];
__device__ float g_wqc[HH*DM2*192];
__device__ float g_wqp[HH*DM2*192];
__device__ float g_woc[HH*DQ2*DM2];
__device__ float g_wop[HH*DQ2*DM2];
__device__ float g_w1c[DF2*DM2];
__device__ float g_w1p[DF2*DM2];
__device__ float g_w2c[DM2*DF2];
__device__ float g_w2p[DM2*DF2];

// ---------------------------------------------------------------------------
__device__ __forceinline__ unsigned f2tf32u(float f) {
    unsigned u;
    asm("cvt.rna.tf32.f32 %0, %1;" : "=r"(u) : "f"(f));
    return u;
}
__device__ __forceinline__ float rtf(float f) { return __uint_as_float(f2tf32u(f)); }

__device__ __forceinline__ void cp16(void* smem, const void* g) {
    unsigned s = (unsigned)__cvta_generic_to_shared(smem);
    asm volatile("cp.async.cg.shared.global [%0], [%1], 16;" :: "r"(s), "l"(g));
}
__device__ __forceinline__ void cp_commit() { asm volatile("cp.async.commit_group;"); }
__device__ __forceinline__ void cp_wait0()  { asm volatile("cp.async.wait_group 0;"); }

__device__ __forceinline__ void ldm_x4(unsigned &r0, unsigned &r1,
                                       unsigned &r2, unsigned &r3,
                                       const unsigned* p) {
    unsigned addr = (unsigned)__cvta_generic_to_shared(p);
    asm volatile("ldmatrix.sync.aligned.m8n8.x4.shared.b16 {%0,%1,%2,%3}, [%4];"
                 : "=r"(r0), "=r"(r1), "=r"(r2), "=r"(r3) : "r"(addr));
}
__device__ __forceinline__ void mma_tf32(float* c, const unsigned* a, const unsigned* b) {
    asm volatile("mma.sync.aligned.m16n8k8.row.col.f32.tf32.tf32.f32 "
                 "{%0,%1,%2,%3}, {%4,%5,%6,%7}, {%8,%9}, {%0,%1,%2,%3};"
                 : "+f"(c[0]), "+f"(c[1]), "+f"(c[2]), "+f"(c[3])
                 : "r"(a[0]), "r"(a[1]), "r"(a[2]), "r"(a[3]),
                   "r"(b[0]), "r"(b[1]));
}

// ---------------------------------------------------------------------------
// Mask canonicalization
// ---------------------------------------------------------------------------
__global__ void mask_probe_k(const void* __restrict__ maskraw) {
    const unsigned int* w = (const unsigned int*)maskraw;
    int tid = threadIdx.x;
    unsigned int v = w[tid];
    int oki = (v == 0u || v == 1u);
    int okf = (v == 0u || v == 0x3F800000u);
    int all_i = __syncthreads_and(oki);
    int all_f = __syncthreads_and(okf);
    if (all_i) {
        const int* wi = (const int*)maskraw;
        for (int i = tid; i < BB*TT; i += 1024) g_maskf[i] = wi[i] ? 1.f : 0.f;
    } else if (all_f) {
        const float* wf = (const float*)maskraw;
        for (int i = tid; i < BB*TT; i += 1024) g_maskf[i] = (wf[i] != 0.f) ? 1.f : 0.f;
    } else {
        const unsigned char* wb = (const unsigned char*)maskraw;
        for (int i = tid; i < BB*TT; i += 1024) g_maskf[i] = wb[i] ? 1.f : 0.f;
    }
}

// ---------------------------------------------------------------------------
// tf32 round-copy (vectorized)
// ---------------------------------------------------------------------------
__global__ void __launch_bounds__(256) cvt_k(const float4* __restrict__ src,
                                             float4* __restrict__ dst, int n4) {
    int i = blockIdx.x * 256 + threadIdx.x;
    if (i < n4) {
        float4 v = src[i];
        v.x = rtf(v.x); v.y = rtf(v.y); v.z = rtf(v.z); v.w = rtf(v.w);
        dst[i] = v;
    }
}

// ---------------------------------------------------------------------------
// TF32 GEMM, 128x64x32 tiles, 8 warps (4Mx2N), cp.async double buffered.
// All operands are pre-rounded tf32 — no cvt in the hot loop.
//  0 QKV  : A=g_xr,  B=g_wq{c,p} per head (n-contig) -> g_q/g_k/g_v (rounded)
//  1 DOTS : A=g_q,   B=g_k (k-contig)                -> g_s (fp32)
//  2 PV   : A=g_s,   B=g_v (n-contig)                -> g_o (rounded)
//  3 OPROJ: A=g_o,   B=g_wo{c,p} (n-contig)          -> g_t1
//  4 FFN1 : A=g_x1r, B=g_w1{c,p} (k-contig) +b relu  -> g_h (rounded)
//  5 FFN2 : A=g_h,   B=g_w2{c,p} (k-contig) +b       -> g_t1
// ---------------------------------------------------------------------------
template<int MODE>
__global__ void __launch_bounds__(256)
gemm_tc(const float* __restrict__ bias0,
        const float* __restrict__ bias1)
{
    constexpr int K = (MODE == 0) ? 512 :
                      (MODE == 1) ? 128 :
                      (MODE == 2) ? 1024 :
                      (MODE == 3) ? 512 :
                      (MODE == 4) ? 512 : 2048;
    constexpr bool B_KCONTIG = (MODE == 1 || MODE == 4 || MODE == 5);

    __shared__ unsigned As[2][128][36];
    __shared__ unsigned Bs[2][64][36];

    const int tid  = threadIdx.x;
    const int lane = tid & 31;
    const int warp = tid >> 5;
    const int wm = (warp & 3) * 32;
    const int wn = (warp >> 2) * 32;
    const int m0 = blockIdx.y * 128;
    const int n0 = blockIdx.x * 64;
    const int z  = blockIdx.z;

    const float* Abase;
    if constexpr (MODE == 0)      Abase = g_xr;
    else if constexpr (MODE == 1) Abase = g_q;
    else if constexpr (MODE == 2) Abase = g_s;
    else if constexpr (MODE == 3) Abase = g_o;
    else if constexpr (MODE == 4) Abase = g_x1r;
    else                          Abase = g_h;

    const float* Wb;
    int bstride;
    if constexpr (MODE == 0) { Wb = ((z >> 3) ? g_wqp : g_wqc) + (size_t)(z & 7) * (DM2 * 192); bstride = 192; }
    else if constexpr (MODE == 1) { Wb = g_k + (size_t)z * (TT*DQ); bstride = DQ;  }
    else if constexpr (MODE == 2) { Wb = g_v + (size_t)z * (TT*DQ); bstride = DQ;  }
    else if constexpr (MODE == 3) { Wb = z ? g_wop : g_woc;         bstride = DM2; }
    else if constexpr (MODE == 4) { Wb = z ? g_w1p : g_w1c;         bstride = DM2; }
    else                          { Wb = z ? g_w2p : g_w2c;         bstride = DF2; }

    float c[2][4][4];
#pragma unroll
    for (int mt = 0; mt < 2; mt++)
#pragma unroll
        for (int nt = 0; nt < 4; nt++)
#pragma unroll
            for (int r = 0; r < 4; r++) c[mt][nt][r] = 0.f;

    const int a_ml = tid >> 3;
    const int a_kq = (tid & 7) << 2;
    const int bk_nl = tid >> 3;
    const int bk_kq = (tid & 7) << 2;
    const int bt_kl = tid >> 4;
    const int bt_nq = (tid & 15) << 2;

    auto a_idx = [&](int m, int k) -> size_t {
        if constexpr (MODE == 0)
            return (size_t)m * DMOD + (size_t)(z >> 3) * DM2 + k;
        else if constexpr (MODE == 1)
            return (size_t)z * (TT*DQ) + (size_t)m * DQ + k;
        else if constexpr (MODE == 2)
            return (size_t)z * ((size_t)TT*TT) + (size_t)m * TT + k;
        else if constexpr (MODE == 3)
            return (size_t)m * DMOD + (size_t)((k >> 6) << 7) + (size_t)z * DQ2 + (k & 63);
        else if constexpr (MODE == 4)
            return (size_t)m * DMOD + (size_t)z * DM2 + k;
        else
            return (size_t)m * (2*DF2) + (size_t)z * DF2 + k;
    };

    auto loadA = [&](int k0, int buf) {
#pragma unroll
        for (int it = 0; it < 4; it++) {
            int m = m0 + a_ml + it * 32;
            cp16(&As[buf][a_ml + it * 32][a_kq], Abase + a_idx(m, k0 + a_kq));
        }
    };
    auto loadB_async = [&](int k0, int buf) {
#pragma unroll
        for (int it = 0; it < 2; it++) {
            int n = n0 + bk_nl + it * 32;
            cp16(&Bs[buf][bk_nl + it * 32][bk_kq], Wb + (size_t)n * bstride + k0 + bk_kq);
        }
    };
    float4 breg[2];
    auto ldgB = [&](int k0) {
#pragma unroll
        for (int it = 0; it < 2; it++) {
            int k = k0 + bt_kl + it * 16;
            breg[it] = *(const float4*)(Wb + (size_t)k * bstride + n0 + bt_nq);
        }
    };
    auto stsB = [&](int buf) {
#pragma unroll
        for (int it = 0; it < 2; it++) {
            int kk = bt_kl + it * 16;
            Bs[buf][bt_nq + 0][kk] = __float_as_uint(breg[it].x);
            Bs[buf][bt_nq + 1][kk] = __float_as_uint(breg[it].y);
            Bs[buf][bt_nq + 2][kk] = __float_as_uint(breg[it].z);
            Bs[buf][bt_nq + 3][kk] = __float_as_uint(breg[it].w);
        }
    };

    // prologue: tile 0
    loadA(0, 0);
    if constexpr (B_KCONTIG) loadB_async(0, 0);
    else { ldgB(0); stsB(0); }
    cp_commit();
    cp_wait0();
    __syncthreads();

    const int grp = lane >> 3;
    const int rr  = lane & 7;

    int cur = 0;
    for (int k0 = 0; k0 < K; k0 += 32) {
        const int nxt = cur ^ 1;
        const bool has_next = (k0 + 32 < K);
        if (has_next) {
            loadA(k0 + 32, nxt);
            if constexpr (B_KCONTIG) loadB_async(k0 + 32, nxt);
            else ldgB(k0 + 32);
            cp_commit();
        }

        // compute on cur
#pragma unroll
        for (int ks = 0; ks < 4; ks++) {
            const int kw = ks * 8;
            unsigned a[2][4];
#pragma unroll
            for (int mt = 0; mt < 2; mt++) {
                const unsigned* p = &As[cur][wm + mt*16 + (grp & 1)*8 + rr][kw + (grp >> 1)*4];
                ldm_x4(a[mt][0], a[mt][1], a[mt][2], a[mt][3], p);
            }
            unsigned b[4][2];
#pragma unroll
            for (int bt = 0; bt < 2; bt++) {
                const unsigned* p = &Bs[cur][wn + bt*16 + (grp >> 1)*8 + rr][kw + (grp & 1)*4];
                unsigned r0, r1, r2, r3;
                ldm_x4(r0, r1, r2, r3, p);
                b[bt*2 + 0][0] = r0; b[bt*2 + 0][1] = r1;
                b[bt*2 + 1][0] = r2; b[bt*2 + 1][1] = r3;
            }
#pragma unroll
            for (int mt = 0; mt < 2; mt++)
#pragma unroll
                for (int nt = 0; nt < 4; nt++)
                    mma_tf32(c[mt][nt], a[mt], b[nt]);
        }

        if (has_next) {
            if constexpr (!B_KCONTIG) stsB(nxt);
            cp_wait0();
        }
        __syncthreads();
        cur = nxt;
    }

    // ---- epilogue ----
    const int g   = lane >> 2;
    const int tig = lane & 3;

#pragma unroll
    for (int mt = 0; mt < 2; mt++) {
#pragma unroll
        for (int nt = 0; nt < 4; nt++) {
            const int mr = m0 + wm + mt*16 + g;
            const int nl = wn + nt*8 + 2*tig;
            float2 lo = make_float2(c[mt][nt][0], c[mt][nt][1]);
            float2 hi = make_float2(c[mt][nt][2], c[mt][nt][3]);

            if constexpr (MODE == 0) {
                const int cc = blockIdx.x;
                const int h = z & 7, sel = z >> 3;
                const float scale = (cc == 0) ? 0.08838834764831845f : 1.0f;
                float* dst = (cc == 0) ? g_q : ((cc == 1) ? g_k : g_v);
                lo.x = rtf(lo.x * scale); lo.y = rtf(lo.y * scale);
                hi.x = rtf(hi.x * scale); hi.y = rtf(hi.y * scale);
                {
                    int b_ = mr >> 10, t_ = mr & 1023;
                    size_t base = ((((size_t)b_*HH + h)*TT + t_) << 7) + ((size_t)sel << 6);
                    *(float2*)(dst + base + nl) = lo;
                }
                {
                    int m2 = mr + 8;
                    int b_ = m2 >> 10, t_ = m2 & 1023;
                    size_t base = ((((size_t)b_*HH + h)*TT + t_) << 7) + ((size_t)sel << 6);
                    *(float2*)(dst + base + nl) = hi;
                }
            } else if constexpr (MODE == 1) {
                size_t base = (size_t)z * ((size_t)TT*TT);
                *(float2*)(g_s + base + (size_t)mr * TT + n0 + nl) = lo;
                *(float2*)(g_s + base + (size_t)(mr+8) * TT + n0 + nl) = hi;
            } else if constexpr (MODE == 2) {
                const int b_ = z >> 3, h = z & 7;
                size_t r0 = ((size_t)(b_*TT + mr)) * DMOD + h*DQ + n0 + nl;
                size_t r1 = ((size_t)(b_*TT + mr + 8)) * DMOD + h*DQ + n0 + nl;
                lo.x = rtf(lo.x); lo.y = rtf(lo.y);
                hi.x = rtf(hi.x); hi.y = rtf(hi.y);
                *(float2*)(g_o + r0) = lo;
                *(float2*)(g_o + r1) = hi;
            } else if constexpr (MODE == 3) {
                size_t r0 = (size_t)mr * DMOD + (size_t)z * DM2 + n0 + nl;
                *(float2*)(g_t1 + r0) = lo;
                *(float2*)(g_t1 + r0 + 8*DMOD) = hi;
            } else if constexpr (MODE == 4) {
                const float* bs = z ? bias1 : bias0;
                float b0 = bs[n0 + nl], b1 = bs[n0 + nl + 1];
                size_t r0 = (size_t)mr * (2*DF2) + (size_t)z * DF2 + n0 + nl;
                float2 o0 = make_float2(rtf(fmaxf(lo.x + b0, 0.f)), rtf(fmaxf(lo.y + b1, 0.f)));
                float2 o1 = make_float2(rtf(fmaxf(hi.x + b0, 0.f)), rtf(fmaxf(hi.y + b1, 0.f)));
                *(float2*)(g_h + r0) = o0;
                *(float2*)(g_h + r0 + (size_t)8 * (2*DF2)) = o1;
            } else {
                const float* bs = z ? bias1 : bias0;
                float b0 = bs[n0 + nl], b1 = bs[n0 + nl + 1];
                size_t r0 = (size_t)mr * DMOD + (size_t)z * DM2 + n0 + nl;
                float2 o0 = make_float2(lo.x + b0, lo.y + b1);
                float2 o1 = make_float2(hi.x + b0, hi.y + b1);
                *(float2*)(g_t1 + r0) = o0;
                *(float2*)(g_t1 + r0 + 8*DMOD) = o1;
            }
        }
    }
}

// ---------------------------------------------------------------------------
// Shuffle-based masked softmax; writes tf32-rounded probs (PV operand)
// ---------------------------------------------------------------------------
__global__ void __launch_bounds__(256) softmax_k()
{
    const int row = blockIdx.x;
    const int b = row >> 13;                    // row = (b*8+h)*1024 + t
    float4* S4 = (float4*)(g_s + (size_t)row * TT);
    const float4* M4 = (const float4*)(g_maskf + b * TT);
    const int tid = threadIdx.x;
    const int lane = tid & 31, wid = tid >> 5;

    __shared__ float red_max[8];
    __shared__ float red_sum[8];

    float4 v = S4[tid];
    float4 m = M4[tid];
    float vals[4];
    vals[0] = (m.x != 0.f) ? v.x : -INFINITY;
    vals[1] = (m.y != 0.f) ? v.y : -INFINITY;
    vals[2] = (m.z != 0.f) ? v.z : -INFINITY;
    vals[3] = (m.w != 0.f) ? v.w : -INFINITY;

    float mx = fmaxf(fmaxf(vals[0], vals[1]), fmaxf(vals[2], vals[3]));
#pragma unroll
    for (int o = 16; o > 0; o >>= 1)
        mx = fmaxf(mx, __shfl_xor_sync(0xFFFFFFFFu, mx, o));
    if (lane == 0) red_max[wid] = mx;
    __syncthreads();
    mx = red_max[0];
#pragma unroll
    for (int i = 1; i < 8; i++) mx = fmaxf(mx, red_max[i]);

    float e[4], sum = 0.f;
#pragma unroll
    for (int i = 0; i < 4; i++) {
        e[i] = (vals[i] == -INFINITY) ? 0.f : __expf(vals[i] - mx);
        sum += e[i];
    }
#pragma unroll
    for (int o = 16; o > 0; o >>= 1)
        sum += __shfl_xor_sync(0xFFFFFFFFu, sum, o);
    if (lane == 0) red_sum[wid] = sum;
    __syncthreads();
    float tot = red_sum[0];
#pragma unroll
    for (int i = 1; i < 8; i++) tot += red_sum[i];
    const float inv = 1.0f / tot;

    float4 o4;
    o4.x = rtf(e[0] * inv); o4.y = rtf(e[1] * inv);
    o4.z = rtf(e[2] * inv); o4.w = rtf(e[3] * inv);
    S4[tid] = o4;
}

// ---------------------------------------------------------------------------
// Fused residual + LayerNorm (shuffle reductions, float4)
// PHASE 0: g_x1 = LN(x + g_t1) fp32, plus g_x1r tf32 copy
// PHASE 1: out  = LN(g_x1 + g_t1)
// ---------------------------------------------------------------------------
template<int PHASE>
__global__ void __launch_bounds__(256)
ln_k(const float* __restrict__ a,
     const float* __restrict__ gamma,
     const float* __restrict__ beta,
     float* __restrict__ outp)
{
    const int row = blockIdx.x;
    const int tid = threadIdx.x;
    const int lane = tid & 31, wid = tid >> 5;
    const float* r1 = (PHASE == 0) ? a : g_x1;

    __shared__ float red1[8];
    __shared__ float red2[8];

    float4 av = ((const float4*)(r1 + (size_t)row * DMOD))[tid];
    float4 tv = ((const float4*)(g_t1 + (size_t)row * DMOD))[tid];
    float v[4] = {av.x + tv.x, av.y + tv.y, av.z + tv.z, av.w + tv.w};

    float s = v[0] + v[1] + v[2] + v[3];
#pragma unroll
    for (int o = 16; o > 0; o >>= 1) s += __shfl_xor_sync(0xFFFFFFFFu, s, o);
    if (lane == 0) red1[wid] = s;
    __syncthreads();
    float tot = red1[0];
#pragma unroll
    for (int i = 1; i < 8; i++) tot += red1[i];
    const float mu = tot * (1.0f / DMOD);

    float vs = 0.f;
#pragma unroll
    for (int i = 0; i < 4; i++) { float d = v[i] - mu; vs += d * d; }
#pragma unroll
    for (int o = 16; o > 0; o >>= 1) vs += __shfl_xor_sync(0xFFFFFFFFu, vs, o);
    if (lane == 0) red2[wid] = vs;
    __syncthreads();
    float vtot = red2[0];
#pragma unroll
    for (int i = 1; i < 8; i++) vtot += red2[i];
    const float rs = rsqrtf(vtot * (1.0f / DMOD) + 1e-5f);

    float4 g4 = ((const float4*)gamma)[tid];
    float4 b4 = ((const float4*)beta)[tid];
    float4 o4;
    o4.x = (v[0] - mu) * rs * g4.x + b4.x;
    o4.y = (v[1] - mu) * rs * g4.y + b4.y;
    o4.z = (v[2] - mu) * rs * g4.z + b4.z;
    o4.w = (v[3] - mu) * rs * g4.w + b4.w;

    if constexpr (PHASE == 0) {
        ((float4*)(g_x1 + (size_t)row * DMOD))[tid] = o4;
        float4 r4;
        r4.x = rtf(o4.x); r4.y = rtf(o4.y); r4.z = rtf(o4.z); r4.w = rtf(o4.w);
        ((float4*)(g_x1r + (size_t)row * DMOD))[tid] = r4;
    } else {
        ((float4*)(outp + (size_t)row * DMOD))[tid] = o4;
    }
}

// ---------------------------------------------------------------------------
extern "C" void kernel_launch(void* const* d_in, const int* in_sizes, int n_in,
                              void* d_out, int out_size)
{
    (void)in_sizes; (void)n_in; (void)out_size;
    const float* x      = (const float*)d_in[0];
    const void*  mask   = d_in[1];
    const float* wqkv_c = (const float*)d_in[2];
    const float* wqkv_p = (const float*)d_in[3];
    const float* wo_c   = (const float*)d_in[4];
    const float* wo_p   = (const float*)d_in[5];
    const float* w1_c   = (const float*)d_in[6];
    const float* b1_c   = (const float*)d_in[7];
    const float* w1_p   = (const float*)d_in[8];
    const float* b1_p   = (const float*)d_in[9];
    const float* w2_c   = (const float*)d_in[10];
    const float* b2_c   = (const float*)d_in[11];
    const float* w2_p   = (const float*)d_in[12];
    const float* b2_p   = (const float*)d_in[13];
    const float* ln1_g  = (const float*)d_in[14];
    const float* ln1_b  = (const float*)d_in[15];
    const float* ln2_g  = (const float*)d_in[16];
    const float* ln2_b  = (const float*)d_in[17];
    float* out = (float*)d_out;

    mask_probe_k<<<1, 1024>>>(mask);

    // tf32 round-copies of external operands
    float* xr; cudaGetSymbolAddress((void**)&xr, g_xr);
    float* wqc; cudaGetSymbolAddress((void**)&wqc, g_wqc);
    float* wqp; cudaGetSymbolAddress((void**)&wqp, g_wqp);
    float* woc; cudaGetSymbolAddress((void**)&woc, g_woc);
    float* wop; cudaGetSymbolAddress((void**)&wop, g_wop);
    float* w1cd; cudaGetSymbolAddress((void**)&w1cd, g_w1c);
    float* w1pd; cudaGetSymbolAddress((void**)&w1pd, g_w1p);
    float* w2cd; cudaGetSymbolAddress((void**)&w2cd, g_w2c);
    float* w2pd; cudaGetSymbolAddress((void**)&w2pd, g_w2p);

    auto cvt = [&](const float* s, float* d, int n) {
        int n4 = n >> 2;
        cvt_k<<<(n4 + 255) / 256, 256>>>((const float4*)s, (float4*)d, n4);
    };
    cvt(x, xr, BT*DMOD);
    cvt(wqkv_c, wqc, HH*DM2*192);
    cvt(wqkv_p, wqp, HH*DM2*192);
    cvt(wo_c, woc, HH*DQ2*DM2);
    cvt(wo_p, wop, HH*DQ2*DM2);
    cvt(w1_c, w1cd, DF2*DM2);
    cvt(w1_p, w1pd, DF2*DM2);
    cvt(w2_c, w2cd, DM2*DF2);
    cvt(w2_p, w2pd, DM2*DF2);

    // 1. QKV
    gemm_tc<0><<<dim3(3, 32, 16), 256>>>(nullptr, nullptr);
    // 2. dots = Q K^T
    gemm_tc<1><<<dim3(16, 8, 32), 256>>>(nullptr, nullptr);
    // 3. masked softmax
    softmax_k<<<BB*HH*TT, 256>>>();
    // 4. O = P V
    gemm_tc<2><<<dim3(2, 8, 32), 256>>>(nullptr, nullptr);
    // 5. O projection
    gemm_tc<3><<<dim3(8, 32, 2), 256>>>(nullptr, nullptr);
    // 6. LN1(x + attn)
    ln_k<0><<<BT, 256>>>(x, ln1_g, ln1_b, nullptr);
    // 7. FFN1 (relu)
    gemm_tc<4><<<dim3(32, 32, 2), 256>>>(b1_c, b1_p);
    // 8. FFN2
    gemm_tc<5><<<dim3(8, 32, 2), 256>>>(b2_c, b2_p);
    // 9. LN2(x1 + ff) -> out
    ln_k<1><<<BT, 256>>>(nullptr, ln2_g, ln2_b, out);
}